// round 6
// baseline (speedup 1.0000x reference)
#include <cuda_runtime.h>
#include <cstdint>

// ---------------- problem constants ----------------
#define Bn 1024
#define Sn 256
#define Dn 512
#define En 16
#define On 512

// ---------------- device scratch (no allocs allowed) ----------------
__device__ float g_wt[(size_t)En * On * Dn];   // 16 MB, tf32-rounded W^T [E,O,D] (K-major)
__device__ int   g_idx[Bn];
__device__ float g_gate[Bn];

// ---------------- PTX helpers ----------------
__device__ __forceinline__ uint32_t smem_u32(const void* p) {
    uint32_t a;
    asm("{ .reg .u64 t; cvta.to.shared.u64 t, %1; cvt.u32.u64 %0, t; }" : "=r"(a) : "l"(p));
    return a;
}

__device__ __forceinline__ float to_tf32(float f) {
    uint32_t u;
    asm("cvt.rna.tf32.f32 %0, %1;" : "=r"(u) : "f"(f));
    return __uint_as_float(u);
}

__device__ __forceinline__ void cvt_tf32_inplace(uint32_t& r) {
    asm("cvt.rna.tf32.f32 %0, %0;" : "+r"(r));
}

// xor-swizzle: 16B segment index ^= (row & 7); conflict-free for ldmatrix columns
#define SWZ(o) ((o) ^ (((o) >> 3) & 0x70))

__device__ __forceinline__ void cp_async16(uint32_t dst, const void* src) {
    asm volatile("cp.async.cg.shared.global [%0], [%1], 16;" :: "r"(dst), "l"(src) : "memory");
}
#define CP_COMMIT() asm volatile("cp.async.commit_group;" ::: "memory")
#define CP_WAIT(n)  asm volatile("cp.async.wait_group %0;"  :: "n"(n) : "memory")

#define LDSM_X4(r0, r1, r2, r3, addr) \
    asm volatile("ldmatrix.sync.aligned.m8n8.x4.shared.b16 {%0,%1,%2,%3}, [%4];" \
        : "=r"(r0), "=r"(r1), "=r"(r2), "=r"(r3) : "r"(addr))

// D(16x8,f32) += A(16x8,tf32) * B(8x8,tf32)
#define MMA_TF32(d, a, b) \
    asm volatile("mma.sync.aligned.m16n8k8.row.col.f32.tf32.tf32.f32 " \
        "{%0,%1,%2,%3}, {%4,%5,%6,%7}, {%8,%9}, {%0,%1,%2,%3};" \
        : "+f"((d)[0]), "+f"((d)[1]), "+f"((d)[2]), "+f"((d)[3]) \
        : "r"((a)[0]), "r"((a)[1]), "r"((a)[2]), "r"((a)[3]), \
          "r"((b)[0]), "r"((b)[1]))

// ---------------- kernel 1: W transpose + tf32 round:  Wt[e][o][d] = rna(We[e][d][o])
__global__ void prep_w_kernel(const float* __restrict__ We) {
    __shared__ float t[32][33];
    int e = blockIdx.z, d0 = blockIdx.x * 32, o0 = blockIdx.y * 32;
    int tx = threadIdx.x, ty = threadIdx.y;
    const float* src = We + (size_t)e * Dn * On;
    float* dst = g_wt + (size_t)e * On * Dn;
    for (int r = ty; r < 32; r += 8)
        t[r][tx] = src[(size_t)(d0 + r) * On + o0 + tx];
    __syncthreads();
    for (int r = ty; r < 32; r += 8)
        dst[(size_t)(o0 + r) * Dn + d0 + tx] = to_tf32(t[tx][r]);
}

// ---------------- kernel 2: routing, 1024 thr: 8 row-groups x 128 float4-cols
__global__ __launch_bounds__(1024, 2) void routing_kernel(
    const float* __restrict__ x, const float* __restrict__ Wg, const float* __restrict__ bg)
{
    __shared__ float spart[8][Dn];      // per-row-group partial sums (16 KB)
    __shared__ float smean[Dn];
    __shared__ float sscore[En];
    const int b   = blockIdx.x;
    const int tid = threadIdx.x;
    const int grp = tid >> 7;           // 0..7: row group (32 rows each)
    const int col = tid & 127;          // float4 column index (128 per row)

    const float4* p = (const float4*)(x + (size_t)b * Sn * Dn)
                      + (size_t)(grp * 32) * 128 + col;

    float4 ae = make_float4(0.f, 0.f, 0.f, 0.f);
    float4 ao = make_float4(0.f, 0.f, 0.f, 0.f);
    #pragma unroll 4
    for (int s = 0; s < 32; s += 2) {
        float4 fe = p[(size_t)s * 128];
        float4 fo = p[(size_t)(s + 1) * 128];
        ae.x += fe.x; ae.y += fe.y; ae.z += fe.z; ae.w += fe.w;
        ao.x += fo.x; ao.y += fo.y; ao.z += fo.z; ao.w += fo.w;
    }
    float4 t4 = make_float4(ae.x + ao.x, ae.y + ao.y, ae.z + ao.z, ae.w + ao.w);
    *(float4*)&spart[grp][col * 4] = t4;
    __syncthreads();

    if (tid < Dn) {
        float s = 0.f;
        #pragma unroll
        for (int g = 0; g < 8; g++) s += spart[g][tid];
        smean[tid] = s * (1.0f / Sn);
    }
    __syncthreads();

    // warps 0..7: fp64 dots, 2 experts each
    const int wid = tid >> 5, lane = tid & 31;
    if (wid < 8) {
        for (int e = wid; e < En; e += 8) {
            double pth = 0.0;
            for (int d = lane; d < Dn; d += 32)
                pth += (double)smean[d] * (double)Wg[d * En + e];
            #pragma unroll
            for (int o = 16; o > 0; o >>= 1)
                pth += __shfl_down_sync(0xFFFFFFFFu, pth, o);
            if (lane == 0) sscore[e] = (float)(pth + (double)bg[e]);
        }
    }
    __syncthreads();

    if (tid == 0) {
        float m = sscore[0];
        int bi = 0;
        #pragma unroll
        for (int e = 1; e < En; e++)
            if (sscore[e] > m) { m = sscore[e]; bi = e; }   // first-max == jnp.argmax
        float den = 0.0f;
        #pragma unroll
        for (int e = 0; e < En; e++) den += expf(sscore[e] - m);
        g_idx[b]  = bi;
        g_gate[b] = 1.0f / den;   // top-1 softmax prob
    }
}

// ---------------- kernel 3: per-batch GEMM, mma.sync tf32 ----------------
// CTA tile M=128 x N=128, K in 16 chunks of 32. 8 warps: 4(M) x 2(N), warp tile 32x64.
// 3 stages x 32KB = 96KB smem -> 2 CTAs/SM. ks-level fragment double buffering.
#define STAGES 3
#define KC 32
#define A_ST (128 * KC * 4)                 // 16 KB
#define B_ST (128 * KC * 4)                 // 16 KB
#define STAGE_BYTES (A_ST + B_ST)           // 32 KB
#define GEMM_SMEM (STAGES * STAGE_BYTES)    // 96 KB
#define NCHUNK (Dn / KC)                    // 16

__global__ __launch_bounds__(256, 2) void moe_gemm_kernel(
    const float* __restrict__ x, const float* __restrict__ be, float* __restrict__ out)
{
    extern __shared__ char smem[];
    const uint32_t sb = smem_u32(smem);
    const int tid  = threadIdx.x;
    const int wid  = tid >> 5;
    const int lane = tid & 31;

    const int bx = blockIdx.x;
    const int b  = bx >> 3;          // batch
    const int mt = (bx >> 2) & 1;    // M tile (2 x 128)
    const int nt = bx & 3;           // N tile (4 x 128)

    const int   e    = g_idx[b];
    const float gate = g_gate[b];

    const char* agbase = (const char*)(x    + ((size_t)b * Sn + mt * 128) * Dn);
    const char* bgbase = (const char*)(g_wt + ((size_t)e * On + nt * 128) * Dn);

    const int warp_m = wid & 3;      // 0..3 -> 32-row slabs
    const int warp_n = wid >> 2;     // 0..1 -> 64-col slabs

    auto load_stage = [&](int c) {
        const int st = c % STAGES;
        const uint32_t abase = sb + st * STAGE_BYTES;
        const uint32_t bbase = abase + A_ST;
        #pragma unroll
        for (int j = 0; j < 4; j++) {               // A: 1024 x 16B over 256 thr
            int idx = j * 256 + tid;
            int row = idx >> 3, seg = idx & 7;
            uint32_t off = row * 128 + seg * 16;
            cp_async16(abase + SWZ(off), agbase + (size_t)row * (Dn * 4) + c * (KC * 4) + seg * 16);
        }
        #pragma unroll
        for (int j = 0; j < 4; j++) {               // B: 1024 x 16B
            int idx = j * 256 + tid;
            int row = idx >> 3, seg = idx & 7;
            uint32_t off = row * 128 + seg * 16;
            cp_async16(bbase + SWZ(off), bgbase + (size_t)row * (Dn * 4) + c * (KC * 4) + seg * 16);
        }
        CP_COMMIT();
    };

    float acc[2][8][4];
    #pragma unroll
    for (int i = 0; i < 2; i++)
        #pragma unroll
        for (int j = 0; j < 8; j++)
            #pragma unroll
            for (int k = 0; k < 4; k++) acc[i][j][k] = 0.f;

    load_stage(0);
    load_stage(1);

    // ldmatrix lane->address precomputation
    const int a_row  = warp_m * 32 + (lane & 15);
    const int a_kh   = (lane >> 4);
    const int b_row0 = warp_n * 64 + ((lane >> 4) << 3) + (lane & 7);
    const int b_kh   = (lane >> 3) & 1;

    uint32_t a[2][2][4];     // [buf][mf][4]
    uint32_t bf[2][8][2];    // [buf][nf][2]

    auto ld_a = [&](int buf, uint32_t abase, int ks) {
        #pragma unroll
        for (int mf = 0; mf < 2; mf++) {
            uint32_t off = (a_row + mf * 16) * 128 + ks * 32 + a_kh * 16;
            LDSM_X4(a[buf][mf][0], a[buf][mf][1], a[buf][mf][2], a[buf][mf][3],
                    abase + SWZ(off));
        }
    };
    auto ld_b = [&](int buf, uint32_t bbase, int ks) {
        #pragma unroll
        for (int np = 0; np < 4; np++) {
            uint32_t off = (b_row0 + np * 16) * 128 + ks * 32 + b_kh * 16;
            LDSM_X4(bf[buf][np * 2][0], bf[buf][np * 2][1],
                    bf[buf][np * 2 + 1][0], bf[buf][np * 2 + 1][1],
                    bbase + SWZ(off));
        }
    };
    auto cvt_a = [&](int buf) {
        #pragma unroll
        for (int mf = 0; mf < 2; mf++)
            #pragma unroll
            for (int i = 0; i < 4; i++) cvt_tf32_inplace(a[buf][mf][i]);
    };

    for (int c = 0; c < NCHUNK; c++) {
        if (c < NCHUNK - 1) { CP_WAIT(1); } else { CP_WAIT(0); }
        __syncthreads();
        // Single barrier per chunk: all warps finished compute(c-1) before any
        // passes this barrier, so overwriting stage (c+2)%3 == (c-1)%3 is safe.
        if (c + 2 < NCHUNK) load_stage(c + 2);

        const uint32_t abase = sb + (c % STAGES) * STAGE_BYTES;
        const uint32_t bbase = abase + A_ST;

        // ks pipeline: frags(ks+1) load + cvt overlap MMAs(ks)
        ld_b(0, bbase, 0);
        ld_a(0, abase, 0);
        cvt_a(0);
        #pragma unroll
        for (int ks = 0; ks < 4; ks++) {
            const int cur = ks & 1, nxt = cur ^ 1;
            if (ks < 3) {
                ld_b(nxt, bbase, ks + 1);
                ld_a(nxt, abase, ks + 1);
            }
            #pragma unroll
            for (int mf = 0; mf < 2; mf++)
                #pragma unroll
                for (int nf = 0; nf < 8; nf++)
                    MMA_TF32(acc[mf][nf], a[cur][mf], bf[cur][nf]);
            if (ks < 3) cvt_a(nxt);
        }
    }

    // epilogue: gate * (acc + bias)
    const int g = lane >> 2, t = lane & 3;
    const float* bias = be + (size_t)e * On + nt * 128 + warp_n * 64;
    float* obase = out + ((size_t)b * Sn + mt * 128 + warp_m * 32 + g) * On
                       + nt * 128 + warp_n * 64;
    #pragma unroll
    for (int mf = 0; mf < 2; mf++) {
        #pragma unroll
        for (int nf = 0; nf < 8; nf++) {
            int col = nf * 8 + t * 2;
            float b0 = __ldg(bias + col);
            float b1 = __ldg(bias + col + 1);
            float2 v0, v1;
            v0.x = gate * (acc[mf][nf][0] + b0);
            v0.y = gate * (acc[mf][nf][1] + b1);
            v1.x = gate * (acc[mf][nf][2] + b0);
            v1.y = gate * (acc[mf][nf][3] + b1);
            *(float2*)(obase + (size_t)(mf * 16) * On + col)     = v0;
            *(float2*)(obase + (size_t)(mf * 16 + 8) * On + col) = v1;
        }
    }
}

// ---------------- entry point ----------------
extern "C" void kernel_launch(void* const* d_in, const int* in_sizes, int n_in,
                              void* d_out, int out_size)
{
    const float* x  = (const float*)d_in[0];
    const float* Wg = (const float*)d_in[1];
    const float* bg = (const float*)d_in[2];
    const float* We = (const float*)d_in[3];
    const float* be = (const float*)d_in[4];
    float* out = (float*)d_out;

    cudaFuncSetAttribute(moe_gemm_kernel,
                         cudaFuncAttributeMaxDynamicSharedMemorySize, GEMM_SMEM);

    routing_kernel<<<Bn, 1024>>>(x, Wg, bg);
    prep_w_kernel<<<dim3(Dn / 32, On / 32, En), dim3(32, 8)>>>(We);
    moe_gemm_kernel<<<Bn * 8, 256, GEMM_SMEM>>>(x, be, out);
}